// round 15
// baseline (speedup 1.0000x reference)
#include <cuda_runtime.h>
#include <cstdint>
#include <math.h>

// Problem shape (fixed by the reference)
#define NB 32
#define NT 2048
#define ND 128
#define CH 8           // timesteps per thread-chunk
#define NC 256         // NT / CH
#define GS 8           // chunk slots per block
#define PAIRS 64       // ND/2 lane pairs
#define THREADS 512    // PAIRS * GS
#define PD 12          // global probe depth (boundary slots only)

// ---------------------------------------------------------------------------
// Single fused kernel. Block = (b, chunk group cg): 8 consecutive chunks x
// 64 lane pairs. Each thread publishes its chunk's mask bits to smem;
// interior slots resolve seeds by scanning smem bits (no global probes).
// Slot 0 / slot 7 run the R13-style global probe and publish external seed
// indices as the block-level fallback. Payload v/t loads stay inline in the
// sweeps; backward sweep re-loads t (L1 hits).
// ---------------------------------------------------------------------------
__global__ void __launch_bounds__(THREADS)
k_all(const float* __restrict__ v, const float* __restrict__ t,
      const void* __restrict__ mraw, float* __restrict__ out) {
    __shared__ unsigned short s_bits[GS][PAIRS];   // bA | bB<<8 per (slot, pair)
    __shared__ int2 s_extf[PAIRS];                 // external fwd seed rows (or -1)
    __shared__ int2 s_extb[PAIRS];                 // external bwd seed rows (or -1)
    __shared__ int s_isb;

    const int tid = threadIdx.x;
    const int dg  = tid & (PAIRS - 1);
    const int i   = tid >> 6;                // chunk slot 0..7 (warp-uniform)
    const int b   = blockIdx.x >> 5;         // NC/GS = 32 groups per batch row
    const int cg  = blockIdx.x & 31;
    const int c   = cg * GS + i;
    const int d2  = dg * 2;

    // ---- mask dtype detection ----
    if (tid < 32) {
        unsigned int w = ((const unsigned int*)mraw)[tid];
        unsigned int any = __ballot_sync(0xffffffffu, w > 1u);
        if (tid == 0) s_isb = (any != 0u);
    }
    __syncthreads();
    const bool isb = (s_isb != 0);

    const float2* v2 = (const float2*)v;
    const float2* t2 = (const float2*)t;
    float2* o2 = (float2*)out;

    const int rb  = b * NT * ND + d2;            // scalar row base (lane 0)
    const int rb2 = b * NT * PAIRS + dg;         // float2/int2 row base
    const int base2 = rb2 + (c * CH) * PAIRS;
    const unsigned char* m8 = (const unsigned char*)mraw;
    const int2* m32 = (const int2*)mraw;

    // ---- chunk mask bits (needed for sweeps anyway) ----
    unsigned int bA = 0, bB = 0;
    if (isb) {
        const unsigned char* pc = m8 + rb + (c * CH) * ND;
#pragma unroll
        for (int tt = 0; tt < CH; ++tt) {
            unsigned int w = *(const unsigned short*)(pc + tt * ND);
            unsigned int r = __vcmpne4(w, 0u);
            bA |= (r & 1u) << tt;
            bB |= ((r >> 8) & 1u) << tt;
        }
    } else {
#pragma unroll
        for (int tt = 0; tt < CH; ++tt) {
            int2 w = m32[base2 + tt * PAIRS];
            bA |= (w.x ? 1u : 0u) << tt;
            bB |= (w.y ? 1u : 0u) << tt;
        }
    }
    s_bits[i][dg] = (unsigned short)(bA | (bB << 8));

    // ---- boundary slots: global probes, publish external seed indices ----
    if (i == 0) {
        const int fstart = cg * (GS * CH) - 1;   // row before block's region
        unsigned int fA = 0, fB = 0;
        const int vf = min(fstart + 1, PD);
        const unsigned int fmask = (vf > 0) ? ((1u << vf) - 1u) : 0u;
        if (isb) {
#pragma unroll
            for (int k = 0; k < PD; ++k) {
                int row = max(fstart - k, 0);
                unsigned int w = *(const unsigned short*)(m8 + rb + row * ND);
                unsigned int r = __vcmpne4(w, 0u);
                fA |= (r & 1u) << k;
                fB |= ((r >> 8) & 1u) << k;
            }
        } else {
#pragma unroll
            for (int k = 0; k < PD; ++k) {
                int row = max(fstart - k, 0);
                int2 w = m32[rb2 + row * PAIRS];
                fA |= (w.x ? 1u : 0u) << k;
                fB |= (w.y ? 1u : 0u) << k;
            }
        }
        fA &= fmask; fB &= fmask;
        int f0 = fA ? fstart - (__ffs(fA) - 1) : -1;
        int f1 = fB ? fstart - (__ffs(fB) - 1) : -1;
        int ti = fstart - PD;
        while ((f0 < 0 || f1 < 0) && ti >= 0) {     // rare deep-miss fallback
            unsigned int a, bb;
            if (isb) {
                unsigned short w = *(const unsigned short*)(m8 + rb + ti * ND);
                a = w & 0xffu; bb = w >> 8;
            } else {
                int2 w = m32[rb2 + ti * PAIRS];
                a = w.x; bb = w.y;
            }
            if (f0 < 0 && a)  f0 = ti;
            if (f1 < 0 && bb) f1 = ti;
            --ti;
        }
        s_extf[dg] = make_int2(f0, f1);
    }
    if (i == GS - 1) {
        const int bstart = (cg + 1) * (GS * CH);  // row after block's region
        unsigned int nA = 0, nB = 0;
        const int vb = min(NT - bstart, PD);
        const unsigned int bmask = (vb > 0) ? ((1u << vb) - 1u) : 0u;
        if (isb) {
#pragma unroll
            for (int k = 0; k < PD; ++k) {
                int row = min(bstart + k, NT - 1);
                unsigned int w = *(const unsigned short*)(m8 + rb + row * ND);
                unsigned int r = __vcmpne4(w, 0u);
                nA |= (r & 1u) << k;
                nB |= ((r >> 8) & 1u) << k;
            }
        } else {
#pragma unroll
            for (int k = 0; k < PD; ++k) {
                int row = min(bstart + k, NT - 1);
                int2 w = m32[rb2 + row * PAIRS];
                nA |= (w.x ? 1u : 0u) << k;
                nB |= (w.y ? 1u : 0u) << k;
            }
        }
        nA &= bmask; nB &= bmask;
        int n0 = nA ? bstart + (__ffs(nA) - 1) : -1;
        int n1 = nB ? bstart + (__ffs(nB) - 1) : -1;
        int ti = bstart + PD;
        while ((n0 < 0 || n1 < 0) && ti < NT) {
            unsigned int a, bb;
            if (isb) {
                unsigned short w = *(const unsigned short*)(m8 + rb + ti * ND);
                a = w & 0xffu; bb = w >> 8;
            } else {
                int2 w = m32[rb2 + ti * PAIRS];
                a = w.x; bb = w.y;
            }
            if (n0 < 0 && a)  n0 = ti;
            if (n1 < 0 && bb) n1 = ti;
            ++ti;
        }
        s_extb[dg] = make_int2(n0, n1);
    }
    __syncthreads();

    // ---- resolve seeds from smem bits (expected ~1.3 hops/direction) ----
    const int crow0 = cg * (GS * CH);
    int f0 = -1, f1 = -1;
    for (int j = i - 1; j >= 0; --j) {
        unsigned int w = s_bits[j][dg];
        unsigned int a = w & 0xffu, bb = (w >> 8) & 0xffu;
        if (f0 < 0 && a)  f0 = crow0 + j * CH + (31 - __clz(a));
        if (f1 < 0 && bb) f1 = crow0 + j * CH + (31 - __clz(bb));
        if (f0 >= 0 && f1 >= 0) break;
    }
    { int2 e = s_extf[dg]; if (f0 < 0) f0 = e.x; if (f1 < 0) f1 = e.y; }

    int n0i = -1, n1i = -1;
    for (int j = i + 1; j < GS; ++j) {
        unsigned int w = s_bits[j][dg];
        unsigned int a = w & 0xffu, bb = (w >> 8) & 0xffu;
        if (n0i < 0 && a)  n0i = crow0 + j * CH + (__ffs(a) - 1);
        if (n1i < 0 && bb) n1i = crow0 + j * CH + (__ffs(bb) - 1);
        if (n0i >= 0 && n1i >= 0) break;
    }
    { int2 e = s_extb[dg]; if (n0i < 0) n0i = e.x; if (n1i < 0) n1i = e.y; }

    // ---- seed gathers ----
    float lx0 = 0.f, lx1 = 0.f, lt0, lt1;
    if (f0 >= 0) { lx0 = v[rb + f0 * ND];     lt0 = t[rb + f0 * ND];     } else lt0 = t[rb];
    if (f1 >= 0) { lx1 = v[rb + 1 + f1 * ND]; lt1 = t[rb + 1 + f1 * ND]; } else lt1 = t[rb + 1];
    float nx0 = 0.f, nx1 = 0.f, nt0, nt1;
    if (n0i >= 0) { nx0 = v[rb + n0i * ND];     nt0 = t[rb + n0i * ND];     } else nt0 = t[rb + (NT - 1) * ND];
    if (n1i >= 0) { nx1 = v[rb + 1 + n1i * ND]; nt1 = t[rb + 1 + n1i * ND]; } else nt1 = t[rb + 1 + (NT - 1) * ND];

    // ---- forward sweep: inclusive forward fill into registers ----
    float2 LX[CH], LT[CH];
#pragma unroll
    for (int tt = 0; tt < CH; ++tt) {
        float2 vv = v2[base2 + tt * PAIRS];
        float2 tv = t2[base2 + tt * PAIRS];
        if ((bA >> tt) & 1u) { lx0 = vv.x; lt0 = tv.x; }
        if ((bB >> tt) & 1u) { lx1 = vv.y; lt1 = tv.y; }
        LX[tt] = make_float2(lx0, lx1);
        LT[tt] = make_float2(lt0, lt1);
    }

    // ---- backward sweep: re-load t (L1 hits), backward fill + interpolate ----
#pragma unroll
    for (int tt = CH - 1; tt >= 0; --tt) {
        float2 tv2 = t2[base2 + tt * PAIRS];   // L1 hit: touched in fwd sweep
        float2 o;
        // lane 0
        {
            float xl = LX[tt].x, tl = LT[tt].x, tv = tv2.x;
            float den = nt0 - tl;
            float r = xl + (nx0 - xl) * __fdividef(tv - tl, den);
            bool ok = (den != 0.f) && isfinite(r);
            if ((bA >> tt) & 1u) {
                o.x = xl;                        // observed: forward fill == v
                nx0 = xl; nt0 = tv;
            } else {
                o.x = ok ? r : 0.f;
            }
        }
        // lane 1
        {
            float xl = LX[tt].y, tl = LT[tt].y, tv = tv2.y;
            float den = nt1 - tl;
            float r = xl + (nx1 - xl) * __fdividef(tv - tl, den);
            bool ok = (den != 0.f) && isfinite(r);
            if ((bB >> tt) & 1u) {
                o.y = xl;
                nx1 = xl; nt1 = tv;
            } else {
                o.y = ok ? r : 0.f;
            }
        }
        o2[base2 + tt * PAIRS] = o;
    }
}

// ---------------------------------------------------------------------------
extern "C" void kernel_launch(void* const* d_in, const int* in_sizes, int n_in,
                              void* d_out, int out_size) {
    const float* values = (const float*)d_in[0];
    const float* times  = (const float*)d_in[1];
    const void*  mask   = d_in[2];

    (void)n_in; (void)in_sizes; (void)out_size;

    // Single fused launch: block = (b, 8-chunk group); streams mask, v, t
    // once; writes out once.
    k_all<<<NB * (NC / GS), THREADS>>>(values, times, mask, (float*)d_out);
}

// round 16
// speedup vs baseline: 1.0609x; 1.0609x over previous
#include <cuda_runtime.h>
#include <cstdint>
#include <math.h>

// Problem shape (fixed by the reference)
#define NB 32
#define NT 2048
#define ND 128
#define CH 8           // timesteps per thread-chunk
#define NC 256         // NT / CH
#define PD 8           // probe depth per direction (single round trip)

// ---------------------------------------------------------------------------
// Single fused kernel. Thread = (b, chunk c, lane pair).
// Probe strategy: one unconditional 8-deep batch per direction with a
// CLAMPED BASE row (immediate-offset loads, no per-row clamps); the bit
// vector is shifted by the base displacement so invalid rows fall off the
// end — no range masks. P(lane fallback) = 2^-8; fallback is a 4-batch loop.
// Payload v/t loads stay inline in the sweeps; backward sweep re-loads t.
// ---------------------------------------------------------------------------
__global__ void __launch_bounds__(128, 9)
k_all(const float* __restrict__ v, const float* __restrict__ t,
      const void* __restrict__ mraw, float* __restrict__ out) {
    // ---- warp-local mask dtype detection (no barrier, no smem) ----
    // int32 0/1 words are always <=1; packed bool bytes give a word >1 over
    // 32 words w.p. 1-(1/8)^32. Bool-as-int32 0/1 takes the int path: correct.
    bool isb;
    {
        unsigned int w = ((const unsigned int*)mraw)[threadIdx.x & 31];
        isb = (__ballot_sync(0xffffffffu, w > 1u) != 0u);
    }

    const int gid = blockIdx.x * 128 + threadIdx.x;
    const int dg = gid & 63;                 // ND/2 = 64 lane pairs
    const int c  = (gid >> 6) & (NC - 1);    // warp-uniform
    const int b  = gid >> 14;                // 6 + log2(NC)
    const int d2 = dg * 2;

    const float2* v2 = (const float2*)v;
    const float2* t2 = (const float2*)t;
    float2* o2 = (float2*)out;

    const int rb  = b * NT * ND + d2;            // scalar row base (lane 0)
    const int rb2 = b * NT * (ND / 2) + dg;      // float2/int2 row base
    const int base2 = rb2 + (c * CH) * (ND / 2);
    const unsigned char* m8 = (const unsigned char*)mraw;
    const int2* m32 = (const int2*)mraw;

    const int fstart = c * CH - 1;
    const int bstart = (c + 1) * CH;
    // Clamped probe bases + bit shifts (shifted-out bits == invalid rows)
    const int fb = max(fstart, PD - 1);
    const int fs = fb - fstart;              // 0 except c==0 (-> PD, zeroes fA)
    const int bb = min(bstart, NT - PD);
    const int bs = bstart - bb;              // 0 except c==NC-1 (-> PD)

    // ---- one latency window: chunk bits + both probe batches ----
    unsigned int bA = 0, bB = 0;     // chunk mask bits
    unsigned int fA = 0, fB = 0;     // forward probe bits (bit k = row fstart-k)
    unsigned int nA = 0, nB = 0;     // backward probe bits (bit k = row bstart+k)

    if (isb) {
        const unsigned char* pc = m8 + rb + (c * CH) * ND;
        const unsigned char* pf = m8 + rb + fb * ND;
        const unsigned char* pb = m8 + rb + bb * ND;
#pragma unroll
        for (int tt = 0; tt < CH; ++tt) {
            unsigned int w = *(const unsigned short*)(pc + tt * ND);
            unsigned int r = __vcmpne4(w, 0u);    // 0xff per nonzero byte
            bA |= (r & 1u) << tt;
            bB |= ((r >> 8) & 1u) << tt;
        }
#pragma unroll
        for (int k = 0; k < PD; ++k) {            // immediate offsets -k*128
            unsigned int w = *(const unsigned short*)(pf - k * ND);
            unsigned int r = __vcmpne4(w, 0u);
            fA |= (r & 1u) << k;
            fB |= ((r >> 8) & 1u) << k;
        }
#pragma unroll
        for (int k = 0; k < PD; ++k) {            // immediate offsets +k*128
            unsigned int w = *(const unsigned short*)(pb + k * ND);
            unsigned int r = __vcmpne4(w, 0u);
            nA |= (r & 1u) << k;
            nB |= ((r >> 8) & 1u) << k;
        }
    } else {
        const int2* pc = m32 + base2;
        const int2* pf = m32 + rb2 + fb * (ND / 2);
        const int2* pb = m32 + rb2 + bb * (ND / 2);
#pragma unroll
        for (int tt = 0; tt < CH; ++tt) {
            int2 w = pc[tt * (ND / 2)];
            bA |= (w.x ? 1u : 0u) << tt;
            bB |= (w.y ? 1u : 0u) << tt;
        }
#pragma unroll
        for (int k = 0; k < PD; ++k) {
            int2 w = pf[-k * (ND / 2)];
            fA |= (w.x ? 1u : 0u) << k;
            fB |= (w.y ? 1u : 0u) << k;
        }
#pragma unroll
        for (int k = 0; k < PD; ++k) {
            int2 w = pb[k * (ND / 2)];
            nA |= (w.x ? 1u : 0u) << k;
            nB |= (w.y ? 1u : 0u) << k;
        }
    }
    // Align probe bits to the true start rows; invalid rows shift out as 0.
    fA >>= fs; fB >>= fs;
    nA >>= bs; nB >>= bs;

    // ---- resolve probe bits -> row indices ----
    int f0 = fA ? fstart - (__ffs(fA) - 1) : -1;
    int f1 = fB ? fstart - (__ffs(fB) - 1) : -1;
    int n0i = nA ? bstart + (__ffs(nA) - 1) : -1;
    int n1i = nB ? bstart + (__ffs(nB) - 1) : -1;

    {   // forward fallback (4-batch): P(lane) ~ 2^-8
        int ti = fstart - PD;
        if (isb) {
            while ((f0 < 0 || f1 < 0) && ti >= 3) {
                unsigned short w0 = *(const unsigned short*)(m8 + rb + (ti    ) * ND);
                unsigned short w1 = *(const unsigned short*)(m8 + rb + (ti - 1) * ND);
                unsigned short w2 = *(const unsigned short*)(m8 + rb + (ti - 2) * ND);
                unsigned short w3 = *(const unsigned short*)(m8 + rb + (ti - 3) * ND);
                if (f0 < 0) f0 = (w0 & 0xffu) ? ti : (w1 & 0xffu) ? ti-1 : (w2 & 0xffu) ? ti-2 : (w3 & 0xffu) ? ti-3 : -1;
                if (f1 < 0) f1 = (w0 >> 8) ? ti : (w1 >> 8) ? ti-1 : (w2 >> 8) ? ti-2 : (w3 >> 8) ? ti-3 : -1;
                ti -= 4;
            }
        } else {
            while ((f0 < 0 || f1 < 0) && ti >= 3) {
                int2 w0 = m32[rb2 + (ti    ) * (ND / 2)];
                int2 w1 = m32[rb2 + (ti - 1) * (ND / 2)];
                int2 w2 = m32[rb2 + (ti - 2) * (ND / 2)];
                int2 w3 = m32[rb2 + (ti - 3) * (ND / 2)];
                if (f0 < 0) f0 = w0.x ? ti : w1.x ? ti-1 : w2.x ? ti-2 : w3.x ? ti-3 : -1;
                if (f1 < 0) f1 = w0.y ? ti : w1.y ? ti-1 : w2.y ? ti-2 : w3.y ? ti-3 : -1;
                ti -= 4;
            }
        }
        while ((f0 < 0 || f1 < 0) && ti >= 0) {    // tail rows (<4 left)
            unsigned int a, bb_;
            if (isb) {
                unsigned short w = *(const unsigned short*)(m8 + rb + ti * ND);
                a = w & 0xffu; bb_ = w >> 8;
            } else {
                int2 w = m32[rb2 + ti * (ND / 2)];
                a = w.x; bb_ = w.y;
            }
            if (f0 < 0 && a)   f0 = ti;
            if (f1 < 0 && bb_) f1 = ti;
            --ti;
        }
    }
    {   // backward fallback (4-batch)
        int ti = bstart + PD;
        if (isb) {
            while ((n0i < 0 || n1i < 0) && ti <= NT - 4) {
                unsigned short w0 = *(const unsigned short*)(m8 + rb + (ti    ) * ND);
                unsigned short w1 = *(const unsigned short*)(m8 + rb + (ti + 1) * ND);
                unsigned short w2 = *(const unsigned short*)(m8 + rb + (ti + 2) * ND);
                unsigned short w3 = *(const unsigned short*)(m8 + rb + (ti + 3) * ND);
                if (n0i < 0) n0i = (w0 & 0xffu) ? ti : (w1 & 0xffu) ? ti+1 : (w2 & 0xffu) ? ti+2 : (w3 & 0xffu) ? ti+3 : -1;
                if (n1i < 0) n1i = (w0 >> 8) ? ti : (w1 >> 8) ? ti+1 : (w2 >> 8) ? ti+2 : (w3 >> 8) ? ti+3 : -1;
                ti += 4;
            }
        } else {
            while ((n0i < 0 || n1i < 0) && ti <= NT - 4) {
                int2 w0 = m32[rb2 + (ti    ) * (ND / 2)];
                int2 w1 = m32[rb2 + (ti + 1) * (ND / 2)];
                int2 w2 = m32[rb2 + (ti + 2) * (ND / 2)];
                int2 w3 = m32[rb2 + (ti + 3) * (ND / 2)];
                if (n0i < 0) n0i = w0.x ? ti : w1.x ? ti+1 : w2.x ? ti+2 : w3.x ? ti+3 : -1;
                if (n1i < 0) n1i = w0.y ? ti : w1.y ? ti+1 : w2.y ? ti+2 : w3.y ? ti+3 : -1;
                ti += 4;
            }
        }
        while ((n0i < 0 || n1i < 0) && ti < NT) {  // tail rows (<4 left)
            unsigned int a, bb_;
            if (isb) {
                unsigned short w = *(const unsigned short*)(m8 + rb + ti * ND);
                a = w & 0xffu; bb_ = w >> 8;
            } else {
                int2 w = m32[rb2 + ti * (ND / 2)];
                a = w.x; bb_ = w.y;
            }
            if (n0i < 0 && a)   n0i = ti;
            if (n1i < 0 && bb_) n1i = ti;
            ++ti;
        }
    }

    // ---- seed gathers (both directions issued together) ----
    float lx0 = 0.f, lx1 = 0.f, lt0, lt1;
    if (f0 >= 0) { lx0 = v[rb + f0 * ND];     lt0 = t[rb + f0 * ND];     } else lt0 = t[rb];
    if (f1 >= 0) { lx1 = v[rb + 1 + f1 * ND]; lt1 = t[rb + 1 + f1 * ND]; } else lt1 = t[rb + 1];
    float nx0 = 0.f, nx1 = 0.f, nt0, nt1;
    if (n0i >= 0) { nx0 = v[rb + n0i * ND];     nt0 = t[rb + n0i * ND];     } else nt0 = t[rb + (NT - 1) * ND];
    if (n1i >= 0) { nx1 = v[rb + 1 + n1i * ND]; nt1 = t[rb + 1 + n1i * ND]; } else nt1 = t[rb + 1 + (NT - 1) * ND];

    // ---- forward sweep: inclusive forward fill into registers ----
    float2 LX[CH], LT[CH];
#pragma unroll
    for (int tt = 0; tt < CH; ++tt) {
        float2 vv = v2[base2 + tt * (ND / 2)];
        float2 tv = t2[base2 + tt * (ND / 2)];
        if ((bA >> tt) & 1u) { lx0 = vv.x; lt0 = tv.x; }
        if ((bB >> tt) & 1u) { lx1 = vv.y; lt1 = tv.y; }
        LX[tt] = make_float2(lx0, lx1);
        LT[tt] = make_float2(lt0, lt1);
    }

    // ---- backward sweep: re-load t (L1 hits), backward fill + interpolate ----
#pragma unroll
    for (int tt = CH - 1; tt >= 0; --tt) {
        float2 tv2 = t2[base2 + tt * (ND / 2)];   // L1 hit: touched in fwd sweep
        float2 o;
        // lane 0
        {
            float xl = LX[tt].x, tl = LT[tt].x, tv = tv2.x;
            float den = nt0 - tl;
            float r = xl + (nx0 - xl) * __fdividef(tv - tl, den);
            bool ok = (den != 0.f) && isfinite(r);
            if ((bA >> tt) & 1u) {
                o.x = xl;                        // observed: forward fill == v
                nx0 = xl; nt0 = tv;
            } else {
                o.x = ok ? r : 0.f;
            }
        }
        // lane 1
        {
            float xl = LX[tt].y, tl = LT[tt].y, tv = tv2.y;
            float den = nt1 - tl;
            float r = xl + (nx1 - xl) * __fdividef(tv - tl, den);
            bool ok = (den != 0.f) && isfinite(r);
            if ((bB >> tt) & 1u) {
                o.y = xl;
                nx1 = xl; nt1 = tv;
            } else {
                o.y = ok ? r : 0.f;
            }
        }
        o2[base2 + tt * (ND / 2)] = o;
    }
}

// ---------------------------------------------------------------------------
extern "C" void kernel_launch(void* const* d_in, const int* in_sizes, int n_in,
                              void* d_out, int out_size) {
    const float* values = (const float*)d_in[0];
    const float* times  = (const float*)d_in[1];
    const void*  mask   = d_in[2];

    (void)n_in; (void)in_sizes; (void)out_size;

    // Single fused launch: streams mask (+probe overage), v, t once;
    // writes out once.
    k_all<<<(NB * NC * (ND / 2)) / 128, 128>>>(values, times, mask, (float*)d_out);
}

// round 17
// speedup vs baseline: 1.0725x; 1.0110x over previous
#include <cuda_runtime.h>
#include <cstdint>
#include <math.h>

// Problem shape (fixed by the reference)
#define NB 32
#define NT 2048
#define ND 128
#define CH 8           // timesteps per thread-chunk
#define NC 256         // NT / CH
#define PD 12          // probe depth per direction (single round trip)

// ---------------------------------------------------------------------------
// Single fused kernel (R13 structure, warp-local detection). Thread =
// (b, chunk c, lane pair). Probe strategy: one unconditional 12-deep batch
// per direction with clamped addresses + post-mask, resolved via __ffs
// (P(lane fallback) = 2^-12). Payload v/t loads stay inline in the sweeps;
// backward sweep re-loads t (L1 hits).
// ---------------------------------------------------------------------------
__global__ void __launch_bounds__(128, 9)
k_all(const float* __restrict__ v, const float* __restrict__ t,
      const void* __restrict__ mraw, float* __restrict__ out) {
    // ---- warp-local mask dtype detection (no barrier, no smem) ----
    // int32 0/1 words are always <=1; packed bool bytes give a word >1 over
    // 32 words w.p. 1-(1/8)^32. Bool-as-int32 0/1 takes the int path: correct.
    bool isb;
    {
        unsigned int w = ((const unsigned int*)mraw)[threadIdx.x & 31];
        isb = (__ballot_sync(0xffffffffu, w > 1u) != 0u);
    }

    const int gid = blockIdx.x * 128 + threadIdx.x;
    const int dg = gid & 63;                 // ND/2 = 64 lane pairs
    const int c  = (gid >> 6) & (NC - 1);    // warp-uniform
    const int b  = gid >> 14;                // 6 + log2(NC)
    const int d2 = dg * 2;

    const float2* v2 = (const float2*)v;
    const float2* t2 = (const float2*)t;
    float2* o2 = (float2*)out;

    const int rb  = b * NT * ND + d2;            // scalar row base (lane 0)
    const int rb2 = b * NT * (ND / 2) + dg;      // float2/int2 row base
    const int base2 = rb2 + (c * CH) * (ND / 2);
    const unsigned char* m8 = (const unsigned char*)mraw;
    const int2* m32 = (const int2*)mraw;

    // Probe ranges + masks (range lengths are multiples of CH=8)
    const int fstart = c * CH - 1;
    const int bstart = (c + 1) * CH;
    const int vf = min(fstart + 1, PD);           // valid forward rows
    const int vb = min(NT - bstart, PD);          // valid backward rows
    const unsigned int fmask = (vf > 0) ? ((1u << vf) - 1u) : 0u;
    const unsigned int bmask = (vb > 0) ? ((1u << vb) - 1u) : 0u;

    // ---- one latency window: chunk bits + both probe batches ----
    unsigned int bA = 0, bB = 0;     // chunk mask bits
    unsigned int fA = 0, fB = 0;     // forward probe bits (bit k = row fstart-k)
    unsigned int nA = 0, nB = 0;     // backward probe bits (bit k = row bstart+k)

    if (isb) {
#pragma unroll
        for (int tt = 0; tt < CH; ++tt) {
            unsigned int w = *(const unsigned short*)(m8 + rb + (c * CH + tt) * ND);
            unsigned int r = __vcmpne4(w, 0u);    // 0xff per nonzero byte
            bA |= (r & 1u) << tt;
            bB |= ((r >> 8) & 1u) << tt;
        }
#pragma unroll
        for (int k = 0; k < PD; ++k) {
            int row = max(fstart - k, 0);         // clamped: always in-bounds
            unsigned int w = *(const unsigned short*)(m8 + rb + row * ND);
            unsigned int r = __vcmpne4(w, 0u);
            fA |= (r & 1u) << k;
            fB |= ((r >> 8) & 1u) << k;
        }
#pragma unroll
        for (int k = 0; k < PD; ++k) {
            int row = min(bstart + k, NT - 1);
            unsigned int w = *(const unsigned short*)(m8 + rb + row * ND);
            unsigned int r = __vcmpne4(w, 0u);
            nA |= (r & 1u) << k;
            nB |= ((r >> 8) & 1u) << k;
        }
    } else {
#pragma unroll
        for (int tt = 0; tt < CH; ++tt) {
            int2 w = m32[base2 + tt * (ND / 2)];
            bA |= (w.x ? 1u : 0u) << tt;
            bB |= (w.y ? 1u : 0u) << tt;
        }
#pragma unroll
        for (int k = 0; k < PD; ++k) {
            int row = max(fstart - k, 0);
            int2 w = m32[rb2 + row * (ND / 2)];
            fA |= (w.x ? 1u : 0u) << k;
            fB |= (w.y ? 1u : 0u) << k;
        }
#pragma unroll
        for (int k = 0; k < PD; ++k) {
            int row = min(bstart + k, NT - 1);
            int2 w = m32[rb2 + row * (ND / 2)];
            nA |= (w.x ? 1u : 0u) << k;
            nB |= (w.y ? 1u : 0u) << k;
        }
    }
    fA &= fmask; fB &= fmask;
    nA &= bmask; nB &= bmask;

    // ---- resolve probe bits -> row indices ----
    int f0 = fA ? fstart - (__ffs(fA) - 1) : -1;
    int f1 = fB ? fstart - (__ffs(fB) - 1) : -1;
    int n0i = nA ? bstart + (__ffs(nA) - 1) : -1;
    int n1i = nB ? bstart + (__ffs(nB) - 1) : -1;

    {   // forward fallback: P ~ 2^-12 per lane
        int ti = fstart - PD;
        while ((f0 < 0 || f1 < 0) && ti >= 0) {
            unsigned int a, bb;
            if (isb) {
                unsigned short w = *(const unsigned short*)(m8 + rb + ti * ND);
                a = w & 0xffu; bb = w >> 8;
            } else {
                int2 w = m32[rb2 + ti * (ND / 2)];
                a = w.x; bb = w.y;
            }
            if (f0 < 0 && a)  f0 = ti;
            if (f1 < 0 && bb) f1 = ti;
            --ti;
        }
    }
    {   // backward fallback
        int ti = bstart + PD;
        while ((n0i < 0 || n1i < 0) && ti < NT) {
            unsigned int a, bb;
            if (isb) {
                unsigned short w = *(const unsigned short*)(m8 + rb + ti * ND);
                a = w & 0xffu; bb = w >> 8;
            } else {
                int2 w = m32[rb2 + ti * (ND / 2)];
                a = w.x; bb = w.y;
            }
            if (n0i < 0 && a)  n0i = ti;
            if (n1i < 0 && bb) n1i = ti;
            ++ti;
        }
    }

    // ---- seed gathers (both directions issued together) ----
    float lx0 = 0.f, lx1 = 0.f, lt0, lt1;
    if (f0 >= 0) { lx0 = v[rb + f0 * ND];     lt0 = t[rb + f0 * ND];     } else lt0 = t[rb];
    if (f1 >= 0) { lx1 = v[rb + 1 + f1 * ND]; lt1 = t[rb + 1 + f1 * ND]; } else lt1 = t[rb + 1];
    float nx0 = 0.f, nx1 = 0.f, nt0, nt1;
    if (n0i >= 0) { nx0 = v[rb + n0i * ND];     nt0 = t[rb + n0i * ND];     } else nt0 = t[rb + (NT - 1) * ND];
    if (n1i >= 0) { nx1 = v[rb + 1 + n1i * ND]; nt1 = t[rb + 1 + n1i * ND]; } else nt1 = t[rb + 1 + (NT - 1) * ND];

    // ---- forward sweep: inclusive forward fill into registers ----
    float2 LX[CH], LT[CH];
#pragma unroll
    for (int tt = 0; tt < CH; ++tt) {
        float2 vv = v2[base2 + tt * (ND / 2)];
        float2 tv = t2[base2 + tt * (ND / 2)];
        if ((bA >> tt) & 1u) { lx0 = vv.x; lt0 = tv.x; }
        if ((bB >> tt) & 1u) { lx1 = vv.y; lt1 = tv.y; }
        LX[tt] = make_float2(lx0, lx1);
        LT[tt] = make_float2(lt0, lt1);
    }

    // ---- backward sweep: re-load t (L1 hits), backward fill + interpolate ----
#pragma unroll
    for (int tt = CH - 1; tt >= 0; --tt) {
        float2 tv2 = t2[base2 + tt * (ND / 2)];   // L1 hit: touched in fwd sweep
        float2 o;
        // lane 0
        {
            float xl = LX[tt].x, tl = LT[tt].x, tv = tv2.x;
            float den = nt0 - tl;
            float r = xl + (nx0 - xl) * __fdividef(tv - tl, den);
            bool ok = (den != 0.f) && isfinite(r);
            if ((bA >> tt) & 1u) {
                o.x = xl;                        // observed: forward fill == v
                nx0 = xl; nt0 = tv;
            } else {
                o.x = ok ? r : 0.f;
            }
        }
        // lane 1
        {
            float xl = LX[tt].y, tl = LT[tt].y, tv = tv2.y;
            float den = nt1 - tl;
            float r = xl + (nx1 - xl) * __fdividef(tv - tl, den);
            bool ok = (den != 0.f) && isfinite(r);
            if ((bB >> tt) & 1u) {
                o.y = xl;
                nx1 = xl; nt1 = tv;
            } else {
                o.y = ok ? r : 0.f;
            }
        }
        o2[base2 + tt * (ND / 2)] = o;
    }
}

// ---------------------------------------------------------------------------
extern "C" void kernel_launch(void* const* d_in, const int* in_sizes, int n_in,
                              void* d_out, int out_size) {
    const float* values = (const float*)d_in[0];
    const float* times  = (const float*)d_in[1];
    const void*  mask   = d_in[2];

    (void)n_in; (void)in_sizes; (void)out_size;

    // Single fused launch: streams mask (+probe overage), v, t once;
    // writes out once.
    k_all<<<(NB * NC * (ND / 2)) / 128, 128>>>(values, times, mask, (float*)d_out);
}